// round 15
// baseline (speedup 1.0000x reference)
#include <cuda_runtime.h>
#include <cuda_fp16.h>
#include <math.h>
#include <stdint.h>

// ---------------------------------------------------------------------------
// Problem constants
// ---------------------------------------------------------------------------
#define LSEQ    2048
#define DMODEL  512
#define DINNER  1024
#define DSTATE  32
#define DCONV   4
#define NPROJ   (2*DSTATE + 1)   // 65
#define LN_EPS  1e-5f
#define NCH     8                // scan chunks
#define CLEN    (LSEQ/NCH)       // 256

// ---------------------------------------------------------------------------
// Scratch
// ---------------------------------------------------------------------------
__device__ float g_xz[LSEQ * 2 * DINNER];     // u = cols[0,1024), z = cols[1024,2048)
__device__ float g_uc[LSEQ * DINNER];         // conv+silu output
__device__ float g_Bt[NCH * DSTATE * CLEN];   // B transposed: [c][s][i]
__device__ float g_Ct[NCH * DSTATE * CLEN];   // C transposed: [c][s][i]
__device__ float4 g_dtu[LSEQ * DINNER];       // {softplus(dt), dt*u, u, 0}
__device__ float g_y [LSEQ * DINNER];         // scan output (pre-gate)
__device__ float g_o [LSEQ * DMODEL];         // pre-LN
__device__ float g_P    [NCH * DINNER * DSTATE];
__device__ float g_Hend [NCH * DINNER * DSTATE];
__device__ float g_Hinit[NCH * DINNER * DSTATE];

// fp16 operands for tensor-core GEMMs (A split hi/lo, B single-rounded)
__device__ __half g_xa_h[LSEQ * DMODEL];        // x hi      [2048][512]
__device__ __half g_xa_l[LSEQ * DMODEL];        // x lo
__device__ __half g_wt_h[2*DINNER * DMODEL];    // W_in^T    [2048][512]
__device__ __half g_ga_h[LSEQ * DINNER];        // gate hi   [2048][1024]
__device__ __half g_ga_l[LSEQ * DINNER];        // gate lo
__device__ __half g_wo_h[DMODEL * DINNER];      // W_out^T   [512][1024]

// ---------------------------------------------------------------------------
// Baseline-PTX tensor helpers
// ---------------------------------------------------------------------------
__device__ __forceinline__ uint32_t s2u(const void* p) {
    uint32_t a;
    asm("{ .reg .u64 t; cvta.to.shared.u64 t, %1; cvt.u32.u64 %0, t; }"
        : "=r"(a) : "l"(p));
    return a;
}

__device__ __forceinline__ void ldmx4(uint32_t& r0, uint32_t& r1,
                                      uint32_t& r2, uint32_t& r3, uint32_t addr) {
    asm volatile("ldmatrix.sync.aligned.m8n8.x4.shared.b16 {%0,%1,%2,%3}, [%4];"
                 : "=r"(r0), "=r"(r1), "=r"(r2), "=r"(r3) : "r"(addr));
}

__device__ __forceinline__ void mma16816(float* c, const uint32_t* a,
                                         const uint32_t* b) {
    asm volatile(
        "mma.sync.aligned.m16n8k16.row.col.f32.f16.f16.f32 "
        "{%0,%1,%2,%3}, {%4,%5,%6,%7}, {%8,%9}, {%0,%1,%2,%3};"
        : "+f"(c[0]), "+f"(c[1]), "+f"(c[2]), "+f"(c[3])
        : "r"(a[0]), "r"(a[1]), "r"(a[2]), "r"(a[3]), "r"(b[0]), "r"(b[1]));
}

__device__ __forceinline__ void cp16(uint32_t saddr, const void* gaddr) {
    asm volatile("cp.async.cg.shared.global [%0], [%1], 16;"
                 :: "r"(saddr), "l"(gaddr));
}
#define CP_COMMIT()  asm volatile("cp.async.commit_group;")
#define CP_WAIT_1()  asm volatile("cp.async.wait_group 1;")
#define CP_WAIT_0()  asm volatile("cp.async.wait_group 0;")

// ---------------------------------------------------------------------------
// Fused conversions: W_in^T (1024 blks) | W_out^T (512 blks) | x hi/lo (1024)
// ---------------------------------------------------------------------------
__global__ __launch_bounds__(256) void cvt_all_kernel(const float* __restrict__ W_in,
                                                      const float* __restrict__ W_out,
                                                      const float* __restrict__ x) {
    __shared__ float t[32][33];
    int bid = blockIdx.x;
    int tid = threadIdx.x;
    if (bid < 1024 + 512) {
        const float* src; __half* th; int R, C, gx, id;
        if (bid < 1024) { src = W_in;  th = g_wt_h; R = DMODEL; C = 2*DINNER; gx = 64; id = bid; }
        else            { src = W_out; th = g_wo_h; R = DINNER; C = DMODEL;  gx = 16; id = bid - 1024; }
        int c0 = (id % gx) * 32, r0 = (id / gx) * 32;
        int tx = tid & 31, ty = tid >> 5;
        for (int j = ty; j < 32; j += 8)
            t[j][tx] = src[(size_t)(r0 + j) * C + c0 + tx];
        __syncthreads();
        for (int j = ty; j < 32; j += 8)
            th[(size_t)(c0 + j) * R + r0 + tx] = __float2half_rn(t[tx][j]);
    } else {
        int i = ((bid - 1536) * 256 + tid) * 4;
        float4 v = *(const float4*)(x + i);
        float vv[4] = {v.x, v.y, v.z, v.w};
        #pragma unroll
        for (int j = 0; j < 4; j++) {
            __half hb = __float2half_rn(vv[j]);
            float r = vv[j] - __half2float(hb);
            g_xa_h[i + j] = hb;
            g_xa_l[i + j] = __float2half_rn(r);
        }
    }
}

// Gate: Ag = y * silu(z) -> hi/lo fp16 [2048][1024]
__global__ __launch_bounds__(256) void gate_cvt_kernel() {
    int i4 = (blockIdx.x * 256 + threadIdx.x) * 4;
    int row = i4 >> 10;
    int col = i4 & 1023;
    float4 y = *(const float4*)(g_y + i4);
    float4 z = *(const float4*)(g_xz + (size_t)row * (2*DINNER) + DINNER + col);
    float yy[4] = {y.x, y.y, y.z, y.w};
    float zz[4] = {z.x, z.y, z.z, z.w};
    #pragma unroll
    for (int j = 0; j < 4; j++) {
        float g = yy[j] * (zz[j] / (1.f + __expf(-zz[j])));
        __half hb = __float2half_rn(g);
        float r = g - __half2float(hb);
        g_ga_h[i4 + j] = hb;
        g_ga_l[i4 + j] = __float2half_rn(r);
    }
}

// ---------------------------------------------------------------------------
// Tensor-core GEMM (fp16x2, mma.sync)
// ---------------------------------------------------------------------------
#define TROW 40                          // padded row stride (fp16 elems)

template<int TM>
__global__ __launch_bounds__(256) void tc_gemm_kernel(
        const __half* __restrict__ Ah, const __half* __restrict__ Al,
        const __half* __restrict__ Bh,
        float* __restrict__ Cout, const float* __restrict__ resid,
        int Ktot, int Nout) {
    constexpr int WR   = TM / 32;
    constexpr int WC   = 8 / WR;
    constexpr int WN   = 128 / WC;
    constexpr int NT   = WN / 8;
    constexpr int NT2  = WN / 16;
    constexpr int ARRA = TM  * TROW * 2;
    constexpr int ARRB = 128 * TROW * 2;
    constexpr int STG  = 2*ARRA + ARRB;

    extern __shared__ char sb[];
    const uint32_t sbase = s2u(sb);

    int tid = threadIdx.x;
    int wid = tid >> 5, lane = tid & 31;
    int wm = wid % WR, wn = wid / WR;

    const int rstr = Ktot / 8;
    const uint4* gA[2] = { (const uint4*)Ah + (size_t)(blockIdx.y*TM)*rstr,
                           (const uint4*)Al + (size_t)(blockIdx.y*TM)*rstr };
    const uint4* gB = (const uint4*)Bh + (size_t)(blockIdx.x*128)*rstr;

    const int NST = Ktot / 32;

    auto prefetch = [&](int kt, int buf) {
        uint32_t s0 = sbase + buf * STG;
        #pragma unroll
        for (int arr = 0; arr < 2; arr++) {
            uint32_t sa = s0 + arr * ARRA;
            #pragma unroll
            for (int i = 0; i < TM*4/256; i++) {
                int idx = tid + i * 256;
                int row = idx >> 2, cj = idx & 3;
                cp16(sa + row * (TROW*2) + cj * 16,
                     gA[arr] + (size_t)row * rstr + kt * 4 + cj);
            }
        }
        uint32_t sbB = s0 + 2*ARRA;
        #pragma unroll
        for (int i = 0; i < 2; i++) {
            int idx = tid + i * 256;
            int row = idx >> 2, cj = idx & 3;
            cp16(sbB + row * (TROW*2) + cj * 16,
                 gB + (size_t)row * rstr + kt * 4 + cj);
        }
        CP_COMMIT();
    };

    float c[2][NT][4];
    #pragma unroll
    for (int mt = 0; mt < 2; mt++)
        #pragma unroll
        for (int nt = 0; nt < NT; nt++)
            #pragma unroll
            for (int j = 0; j < 4; j++) c[mt][nt][j] = 0.f;

    prefetch(0, 0);

    for (int kt = 0; kt < NST; kt++) {
        int buf = kt & 1;
        if (kt + 1 < NST) { prefetch(kt + 1, buf ^ 1); CP_WAIT_1(); }
        else              { CP_WAIT_0(); }
        __syncthreads();

        uint32_t sAh = sbase + buf*STG;
        uint32_t sAl = sAh + ARRA;
        uint32_t sBh = sAl + ARRA;

        int a_row = (lane & 15);
        int a_kof = (lane >> 4) * 8;
        int b_row = ((lane >> 4) & 1) * 8 + (lane & 7);
        int b_kof = ((lane >> 3) & 1) * 8;

        #pragma unroll
        for (int ks = 0; ks < 32; ks += 16) {
            uint32_t ah[2][4], al[2][4], bh[NT2][4];
            #pragma unroll
            for (int mt = 0; mt < 2; mt++) {
                uint32_t ro = (uint32_t)(wm*32 + mt*16 + a_row) * (TROW*2)
                            + (uint32_t)(ks + a_kof) * 2;
                ldmx4(ah[mt][0], ah[mt][1], ah[mt][2], ah[mt][3], sAh + ro);
                ldmx4(al[mt][0], al[mt][1], al[mt][2], al[mt][3], sAl + ro);
            }
            #pragma unroll
            for (int nt2 = 0; nt2 < NT2; nt2++) {
                uint32_t ro = (uint32_t)(wn*WN + nt2*16 + b_row) * (TROW*2)
                            + (uint32_t)(ks + b_kof) * 2;
                ldmx4(bh[nt2][0], bh[nt2][1], bh[nt2][2], bh[nt2][3], sBh + ro);
            }
            #pragma unroll
            for (int nt2 = 0; nt2 < NT2; nt2++)
                #pragma unroll
                for (int mt = 0; mt < 2; mt++) {
                    mma16816(c[mt][2*nt2],   ah[mt], bh[nt2]);
                    mma16816(c[mt][2*nt2+1], ah[mt], bh[nt2] + 2);
                }
            #pragma unroll
            for (int nt2 = 0; nt2 < NT2; nt2++)
                #pragma unroll
                for (int mt = 0; mt < 2; mt++) {
                    mma16816(c[mt][2*nt2],   al[mt], bh[nt2]);
                    mma16816(c[mt][2*nt2+1], al[mt], bh[nt2] + 2);
                }
        }
        __syncthreads();
    }

    int lq = lane >> 2, lr = lane & 3;
    #pragma unroll
    for (int mt = 0; mt < 2; mt++) {
        #pragma unroll
        for (int half = 0; half < 2; half++) {
            int m = blockIdx.y*TM + wm*32 + mt*16 + lq + half*8;
            size_t ro = (size_t)m * Nout + blockIdx.x*128 + wn*WN;
            #pragma unroll
            for (int nt = 0; nt < NT; nt++) {
                int n = nt*8 + lr*2;
                float v0 = c[mt][nt][2*half + 0];
                float v1 = c[mt][nt][2*half + 1];
                if (resid) {
                    v0 += resid[ro + n];
                    v1 += resid[ro + n + 1];
                }
                Cout[ro + n]     = v0;
                Cout[ro + n + 1] = v1;
            }
        }
    }
}

#define SMEM_T128 (2*(2*128*TROW*2 + 128*TROW*2))   // 61440
#define SMEM_T64  (2*(2*64*TROW*2  + 128*TROW*2))   // 40960

// ---------------------------------------------------------------------------
// Fused conv + x_dbc projection + dtu.  One block = 8 sequence rows.
// B/C written transposed [c][s][i]; dtu written as float4 {dt, dt*u, u, 0}.
// ---------------------------------------------------------------------------
#define SUROW 1032
#define SXDBC ((11*1024 + 8*SUROW) * 4)

__global__ void xdbc_conv_kernel(const float* __restrict__ cw,
                                 const float* __restrict__ cb,
                                 const float* __restrict__ Wx,
                                 const float* __restrict__ Wdt,
                                 const float* __restrict__ bdt) {
    extern __shared__ float xsm[];
    float* sxz = xsm;                 // [11][1024]
    float* su  = xsm + 11*1024;       // [8][SUROW]
    __shared__ float sdt[8];

    int tx = threadIdx.x;   // 0..64
    int ty = threadIdx.y;   // 0..3
    int tid = ty * 65 + tx; // 0..259
    int row0 = blockIdx.x * 8;

    for (int un = tid; un < 11*256; un += 260) {
        int r = un >> 8, c4 = (un & 255) * 4;
        int l = row0 - 3 + r;
        float4 v = make_float4(0.f, 0.f, 0.f, 0.f);
        if (l >= 0)
            v = *(const float4*)(g_xz + (size_t)l*(2*DINNER) + c4);
        *(float4*)(sxz + r*1024 + c4) = v;
    }
    __syncthreads();

    for (int un = tid; un < 8*256; un += 260) {
        int r = un >> 8, c4 = (un & 255) * 4;
        float4 wv0 = *(const float4*)(cw + (c4+0)*DCONV);
        float4 wv1 = *(const float4*)(cw + (c4+1)*DCONV);
        float4 wv2 = *(const float4*)(cw + (c4+2)*DCONV);
        float4 wv3 = *(const float4*)(cw + (c4+3)*DCONV);
        float w0[4] = {wv0.x, wv0.y, wv0.z, wv0.w};
        float w1[4] = {wv1.x, wv1.y, wv1.z, wv1.w};
        float w2[4] = {wv2.x, wv2.y, wv2.z, wv2.w};
        float w3[4] = {wv3.x, wv3.y, wv3.z, wv3.w};
        float4 bias = *(const float4*)(cb + c4);
        float a0 = bias.x, a1 = bias.y, a2 = bias.z, a3 = bias.w;
        #pragma unroll
        for (int j = 0; j < DCONV; j++) {
            const float* xp = sxz + (r + j)*1024 + c4;
            a0 = fmaf(xp[0], w0[j], a0);
            a1 = fmaf(xp[1], w1[j], a1);
            a2 = fmaf(xp[2], w2[j], a2);
            a3 = fmaf(xp[3], w3[j], a3);
        }
        float4 o;
        o.x = a0 / (1.f + __expf(-a0));
        o.y = a1 / (1.f + __expf(-a1));
        o.z = a2 / (1.f + __expf(-a2));
        o.w = a3 / (1.f + __expf(-a3));
        *(float4*)(su + r*SUROW + c4) = o;
        *(float4*)(g_uc + (size_t)(row0 + r)*DINNER + c4) = o;
    }
    __syncthreads();

    float acc0 = 0.f, acc1 = 0.f;
    for (int k = 0; k < DINNER; k++) {
        float w = Wx[(size_t)k*NPROJ + tx];
        acc0 = fmaf(su[ty*SUROW + k],     w, acc0);
        acc1 = fmaf(su[(4+ty)*SUROW + k], w, acc1);
    }
    {
        int l0a = row0 + ty, l1a = row0 + 4 + ty;
        int c0a = l0a >> 8, i0a = l0a & 255;
        int c1a = l1a >> 8, i1a = l1a & 255;
        if (tx < DSTATE) {
            g_Bt[(c0a*DSTATE + tx)*CLEN + i0a] = acc0;
            g_Bt[(c1a*DSTATE + tx)*CLEN + i1a] = acc1;
        } else if (tx < 2*DSTATE) {
            g_Ct[(c0a*DSTATE + tx - DSTATE)*CLEN + i0a] = acc0;
            g_Ct[(c1a*DSTATE + tx - DSTATE)*CLEN + i1a] = acc1;
        } else {
            sdt[ty] = acc0; sdt[4 + ty] = acc1;
        }
    }
    __syncthreads();

    // dtu: one channel per idx, float4 {dt, dt*u, u, 0}
    for (int idx = tid; idx < 8*1024; idx += 260) {
        int r  = idx >> 10;
        int dd = idx & 1023;
        int l  = row0 + r;
        float raw = sdt[r];
        float xv = fmaf(raw, Wdt[dd], bdt[dd]);
        float dt = (xv > 15.f) ? xv : __logf(1.f + __expf(xv));
        float uu = su[r*SUROW + dd];
        g_dtu[(size_t)l*DINNER + dd] = make_float4(dt, dt * uu, uu, 0.f);
    }
}

// ---------------------------------------------------------------------------
// Chunked selective scan (1 chunk/warp; float4 B loads cover 4 steps)
// ---------------------------------------------------------------------------
__global__ __launch_bounds__(256, 4) void scanA_kernel(const float* __restrict__ A_log) {
    int w = (blockIdx.x * 256 + threadIdx.x) >> 5;
    int lane = threadIdx.x & 31;
    int d = w & (DINNER-1);
    int c = w >> 10;

    float a = -__expf(A_log[d*DSTATE + lane]);
    const float4* pdtu = g_dtu + (size_t)c*CLEN*DINNER + d;
    const float4* pBt  = (const float4*)(g_Bt + ((size_t)c*DSTATE + lane)*CLEN);

    float h = 0.f, S = 0.f;
    #pragma unroll 2
    for (int i = 0; i < CLEN; i += 4) {
        float4 b4 = __ldg(pBt + (i >> 2));
        float bj[4] = {b4.x, b4.y, b4.z, b4.w};
        #pragma unroll
        for (int j = 0; j < 4; j++) {
            float4 t = __ldg(pdtu + (size_t)(i + j)*DINNER);
            float dA = __expf(t.x * a);
            h = fmaf(dA, h, t.y * bj[j]);
            S += t.x;
        }
    }
    int idx = (c*DINNER + d)*DSTATE + lane;
    g_P[idx]    = __expf(a * S);
    g_Hend[idx] = h;
}

__global__ __launch_bounds__(256) void scanB_kernel() {
    int t = blockIdx.x * 256 + threadIdx.x;
    float hin = 0.f;
    g_Hinit[t] = 0.f;
    #pragma unroll
    for (int c = 1; c < NCH; c++) {
        hin = fmaf(g_P[(c-1)*DINNER*DSTATE + t], hin, g_Hend[(c-1)*DINNER*DSTATE + t]);
        g_Hinit[c*DINNER*DSTATE + t] = hin;
    }
}

__global__ __launch_bounds__(256, 4) void scanC_kernel(const float* __restrict__ A_log,
                                                       const float* __restrict__ Dvec) {
    int w = (blockIdx.x * 256 + threadIdx.x) >> 5;
    int lane = threadIdx.x & 31;
    int d = w & (DINNER-1);
    int c = w >> 10;

    float a  = -__expf(A_log[d*DSTATE + lane]);
    float Dd = Dvec[d];
    float h  = g_Hinit[(c*DINNER + d)*DSTATE + lane];

    const float4* pdtu = g_dtu + (size_t)c*CLEN*DINNER + d;
    const float4* pBt  = (const float4*)(g_Bt + ((size_t)c*DSTATE + lane)*CLEN);
    const float4* pCt  = (const float4*)(g_Ct + ((size_t)c*DSTATE + lane)*CLEN);
    float* py = g_y + (size_t)c*CLEN*DINNER + d;

    for (int i = 0; i < CLEN; i += 4) {
        float4 b4 = __ldg(pBt + (i >> 2));
        float4 c4 = __ldg(pCt + (i >> 2));
        float bj[4] = {b4.x, b4.y, b4.z, b4.w};
        float cj[4] = {c4.x, c4.y, c4.z, c4.w};
        #pragma unroll
        for (int j = 0; j < 4; j++) {
            float4 t = __ldg(pdtu + (size_t)(i + j)*DINNER);
            float dA = __expf(t.x * a);
            h = fmaf(dA, h, t.y * bj[j]);
            float p = h * cj[j];
            #pragma unroll
            for (int o = 16; o; o >>= 1)
                p += __shfl_xor_sync(0xffffffffu, p, o);
            if (lane == 0)
                py[(size_t)(i + j)*DINNER] = fmaf(t.z, Dd, p);
        }
    }
}

// ---------------------------------------------------------------------------
// LayerNorm over 512 per row
// ---------------------------------------------------------------------------
__global__ __launch_bounds__(256) void ln_kernel(const float* __restrict__ g,
                                                 const float* __restrict__ b,
                                                 float* __restrict__ out) {
    int l = blockIdx.x;
    int t = threadIdx.x;
    __shared__ float sm[8];

    float v0 = g_o[(size_t)l*DMODEL + t];
    float v1 = g_o[(size_t)l*DMODEL + 256 + t];

    float s = v0 + v1;
    #pragma unroll
    for (int o = 16; o; o >>= 1) s += __shfl_xor_sync(0xffffffffu, s, o);
    if ((t & 31) == 0) sm[t >> 5] = s;
    __syncthreads();
    float tot = 0.f;
    #pragma unroll
    for (int w = 0; w < 8; w++) tot += sm[w];
    float mu = tot * (1.f / DMODEL);

    float d0 = v0 - mu, d1 = v1 - mu;
    float q = d0*d0 + d1*d1;
    __syncthreads();
    #pragma unroll
    for (int o = 16; o; o >>= 1) q += __shfl_xor_sync(0xffffffffu, q, o);
    if ((t & 31) == 0) sm[t >> 5] = q;
    __syncthreads();
    float qtot = 0.f;
    #pragma unroll
    for (int w = 0; w < 8; w++) qtot += sm[w];
    float var = qtot * (1.f / DMODEL);
    float rstd = rsqrtf(var + LN_EPS);

    out[(size_t)l*DMODEL + t]       = d0 * rstd * g[t]       + b[t];
    out[(size_t)l*DMODEL + 256 + t] = d1 * rstd * g[t + 256] + b[t + 256];
}

// ---------------------------------------------------------------------------
// Launch.  inputs: 0:x 1:W_in 2:conv_w 3:conv_b 4:W_x 5:W_dt 6:b_dt 7:A_log
//          8:D 9:W_out 10:ln_g 11:ln_b
// ---------------------------------------------------------------------------
extern "C" void kernel_launch(void* const* d_in, const int* in_sizes, int n_in,
                              void* d_out, int out_size) {
    const float* x      = (const float*)d_in[0];
    const float* W_in   = (const float*)d_in[1];
    const float* conv_w = (const float*)d_in[2];
    const float* conv_b = (const float*)d_in[3];
    const float* W_x    = (const float*)d_in[4];
    const float* W_dt   = (const float*)d_in[5];
    const float* b_dt   = (const float*)d_in[6];
    const float* A_log  = (const float*)d_in[7];
    const float* Dvec   = (const float*)d_in[8];
    const float* W_out  = (const float*)d_in[9];
    const float* ln_g   = (const float*)d_in[10];
    const float* ln_b   = (const float*)d_in[11];
    float* out = (float*)d_out;

    static int smem_set = 0;
    if (!smem_set) {
        cudaFuncSetAttribute(tc_gemm_kernel<128>,
                             cudaFuncAttributeMaxDynamicSharedMemorySize, SMEM_T128);
        cudaFuncSetAttribute(tc_gemm_kernel<64>,
                             cudaFuncAttributeMaxDynamicSharedMemorySize, SMEM_T64);
        cudaFuncSetAttribute(xdbc_conv_kernel,
                             cudaFuncAttributeMaxDynamicSharedMemorySize, SXDBC);
        smem_set = 1;
    }

    __half *xa_h, *xa_l, *wt_h, *ga_h, *ga_l, *wo_h;
    cudaGetSymbolAddress((void**)&xa_h, g_xa_h);
    cudaGetSymbolAddress((void**)&xa_l, g_xa_l);
    cudaGetSymbolAddress((void**)&wt_h, g_wt_h);
    cudaGetSymbolAddress((void**)&ga_h, g_ga_h);
    cudaGetSymbolAddress((void**)&ga_l, g_ga_l);
    cudaGetSymbolAddress((void**)&wo_h, g_wo_h);
    float *xz_p, *o_p;
    cudaGetSymbolAddress((void**)&xz_p, g_xz);
    cudaGetSymbolAddress((void**)&o_p, g_o);

    // 1: all conversions
    cvt_all_kernel<<<2560, 256>>>(W_in, W_out, x);
    // 2: GEMM1
    tc_gemm_kernel<128><<<dim3(16,16), 256, SMEM_T128>>>(
        xa_h, xa_l, wt_h, xz_p, nullptr, DMODEL, 2*DINNER);
    // 3: fused conv + projection + dtu
    xdbc_conv_kernel<<<LSEQ/8, dim3(65, 4), SXDBC>>>(conv_w, conv_b, W_x, W_dt, b_dt);
    // 4: scanA  (ncu capture lands here)
    scanA_kernel<<<(DINNER*NCH)/8, 256>>>(A_log);
    // 5-6: combine + rescan
    scanB_kernel<<<(DINNER*DSTATE)/256, 256>>>();
    scanC_kernel<<<(DINNER*NCH)/8, 256>>>(A_log, Dvec);
    // 7: gate conversion
    gate_cvt_kernel<<<(LSEQ*DINNER/4)/256, 256>>>();
    // 8: GEMM2
    tc_gemm_kernel<64><<<dim3(4,32), 256, SMEM_T64>>>(
        ga_h, ga_l, wo_h, o_p, x, DINNER, DMODEL);
    // 9: LayerNorm
    ln_kernel<<<LSEQ, 256>>>(ln_g, ln_b, out);
}

// round 16
// speedup vs baseline: 1.4492x; 1.4492x over previous
#include <cuda_runtime.h>
#include <cuda_fp16.h>
#include <math.h>
#include <stdint.h>

// ---------------------------------------------------------------------------
// Problem constants
// ---------------------------------------------------------------------------
#define LSEQ    2048
#define DMODEL  512
#define DINNER  1024
#define DSTATE  32
#define DCONV   4
#define NPROJ   (2*DSTATE + 1)   // 65
#define LN_EPS  1e-5f
#define NCH     8                // scan chunks
#define CLEN    (LSEQ/NCH)       // 256
#define DHALF   512              // channel pairs (d, d+512)

// ---------------------------------------------------------------------------
// Scratch
// ---------------------------------------------------------------------------
__device__ float g_xz[LSEQ * 2 * DINNER];     // u = cols[0,1024), z = cols[1024,2048)
__device__ float g_uc[LSEQ * DINNER];         // conv+silu output
__device__ float g_B [LSEQ * DSTATE];         // [l][s]  (lane-coalesced)
__device__ float g_C [LSEQ * DSTATE];
__device__ float4 g_dtu[LSEQ * DHALF];        // [l][dp] {dt0, dt0*u0, dt1, dt1*u1}
__device__ float g_y [LSEQ * DINNER];         // scan output (pre-gate)
__device__ float g_o [LSEQ * DMODEL];         // pre-LN
__device__ float g_P    [NCH * DINNER * DSTATE];
__device__ float g_Hend [NCH * DINNER * DSTATE];
__device__ float g_Hinit[NCH * DINNER * DSTATE];

// fp16 operands for tensor-core GEMMs (A split hi/lo, B single-rounded)
__device__ __half g_xa_h[LSEQ * DMODEL];        // x hi      [2048][512]
__device__ __half g_xa_l[LSEQ * DMODEL];        // x lo
__device__ __half g_wt_h[2*DINNER * DMODEL];    // W_in^T    [2048][512]
__device__ __half g_ga_h[LSEQ * DINNER];        // gate hi   [2048][1024]
__device__ __half g_ga_l[LSEQ * DINNER];        // gate lo
__device__ __half g_wo_h[DMODEL * DINNER];      // W_out^T   [512][1024]

// ---------------------------------------------------------------------------
// Baseline-PTX tensor helpers
// ---------------------------------------------------------------------------
__device__ __forceinline__ uint32_t s2u(const void* p) {
    uint32_t a;
    asm("{ .reg .u64 t; cvta.to.shared.u64 t, %1; cvt.u32.u64 %0, t; }"
        : "=r"(a) : "l"(p));
    return a;
}

__device__ __forceinline__ void ldmx4(uint32_t& r0, uint32_t& r1,
                                      uint32_t& r2, uint32_t& r3, uint32_t addr) {
    asm volatile("ldmatrix.sync.aligned.m8n8.x4.shared.b16 {%0,%1,%2,%3}, [%4];"
                 : "=r"(r0), "=r"(r1), "=r"(r2), "=r"(r3) : "r"(addr));
}

__device__ __forceinline__ void mma16816(float* c, const uint32_t* a,
                                         const uint32_t* b) {
    asm volatile(
        "mma.sync.aligned.m16n8k16.row.col.f32.f16.f16.f32 "
        "{%0,%1,%2,%3}, {%4,%5,%6,%7}, {%8,%9}, {%0,%1,%2,%3};"
        : "+f"(c[0]), "+f"(c[1]), "+f"(c[2]), "+f"(c[3])
        : "r"(a[0]), "r"(a[1]), "r"(a[2]), "r"(a[3]), "r"(b[0]), "r"(b[1]));
}

__device__ __forceinline__ void cp16(uint32_t saddr, const void* gaddr) {
    asm volatile("cp.async.cg.shared.global [%0], [%1], 16;"
                 :: "r"(saddr), "l"(gaddr));
}
#define CP_COMMIT()  asm volatile("cp.async.commit_group;")
#define CP_WAIT_1()  asm volatile("cp.async.wait_group 1;")
#define CP_WAIT_0()  asm volatile("cp.async.wait_group 0;")

// ---------------------------------------------------------------------------
// Fused conversions: W_in^T (1024 blks) | W_out^T (512 blks) | x hi/lo (1024)
// ---------------------------------------------------------------------------
__global__ __launch_bounds__(256) void cvt_all_kernel(const float* __restrict__ W_in,
                                                      const float* __restrict__ W_out,
                                                      const float* __restrict__ x) {
    __shared__ float t[32][33];
    int bid = blockIdx.x;
    int tid = threadIdx.x;
    if (bid < 1024 + 512) {
        const float* src; __half* th; int R, C, gx, id;
        if (bid < 1024) { src = W_in;  th = g_wt_h; R = DMODEL; C = 2*DINNER; gx = 64; id = bid; }
        else            { src = W_out; th = g_wo_h; R = DINNER; C = DMODEL;  gx = 16; id = bid - 1024; }
        int c0 = (id % gx) * 32, r0 = (id / gx) * 32;
        int tx = tid & 31, ty = tid >> 5;
        for (int j = ty; j < 32; j += 8)
            t[j][tx] = src[(size_t)(r0 + j) * C + c0 + tx];
        __syncthreads();
        for (int j = ty; j < 32; j += 8)
            th[(size_t)(c0 + j) * R + r0 + tx] = __float2half_rn(t[tx][j]);
    } else {
        int i = ((bid - 1536) * 256 + tid) * 4;
        float4 v = *(const float4*)(x + i);
        float vv[4] = {v.x, v.y, v.z, v.w};
        #pragma unroll
        for (int j = 0; j < 4; j++) {
            __half hb = __float2half_rn(vv[j]);
            float r = vv[j] - __half2float(hb);
            g_xa_h[i + j] = hb;
            g_xa_l[i + j] = __float2half_rn(r);
        }
    }
}

// Gate: Ag = y * silu(z) -> hi/lo fp16 [2048][1024]
__global__ __launch_bounds__(256) void gate_cvt_kernel() {
    int i4 = (blockIdx.x * 256 + threadIdx.x) * 4;
    int row = i4 >> 10;
    int col = i4 & 1023;
    float4 y = *(const float4*)(g_y + i4);
    float4 z = *(const float4*)(g_xz + (size_t)row * (2*DINNER) + DINNER + col);
    float yy[4] = {y.x, y.y, y.z, y.w};
    float zz[4] = {z.x, z.y, z.z, z.w};
    #pragma unroll
    for (int j = 0; j < 4; j++) {
        float g = yy[j] * (zz[j] / (1.f + __expf(-zz[j])));
        __half hb = __float2half_rn(g);
        float r = g - __half2float(hb);
        g_ga_h[i4 + j] = hb;
        g_ga_l[i4 + j] = __float2half_rn(r);
    }
}

// ---------------------------------------------------------------------------
// Tensor-core GEMM (fp16x2, mma.sync)
// ---------------------------------------------------------------------------
#define TROW 40                          // padded row stride (fp16 elems)

template<int TM>
__global__ __launch_bounds__(256) void tc_gemm_kernel(
        const __half* __restrict__ Ah, const __half* __restrict__ Al,
        const __half* __restrict__ Bh,
        float* __restrict__ Cout, const float* __restrict__ resid,
        int Ktot, int Nout) {
    constexpr int WR   = TM / 32;
    constexpr int WC   = 8 / WR;
    constexpr int WN   = 128 / WC;
    constexpr int NT   = WN / 8;
    constexpr int NT2  = WN / 16;
    constexpr int ARRA = TM  * TROW * 2;
    constexpr int ARRB = 128 * TROW * 2;
    constexpr int STG  = 2*ARRA + ARRB;

    extern __shared__ char sb[];
    const uint32_t sbase = s2u(sb);

    int tid = threadIdx.x;
    int wid = tid >> 5, lane = tid & 31;
    int wm = wid % WR, wn = wid / WR;

    const int rstr = Ktot / 8;
    const uint4* gA[2] = { (const uint4*)Ah + (size_t)(blockIdx.y*TM)*rstr,
                           (const uint4*)Al + (size_t)(blockIdx.y*TM)*rstr };
    const uint4* gB = (const uint4*)Bh + (size_t)(blockIdx.x*128)*rstr;

    const int NST = Ktot / 32;

    auto prefetch = [&](int kt, int buf) {
        uint32_t s0 = sbase + buf * STG;
        #pragma unroll
        for (int arr = 0; arr < 2; arr++) {
            uint32_t sa = s0 + arr * ARRA;
            #pragma unroll
            for (int i = 0; i < TM*4/256; i++) {
                int idx = tid + i * 256;
                int row = idx >> 2, cj = idx & 3;
                cp16(sa + row * (TROW*2) + cj * 16,
                     gA[arr] + (size_t)row * rstr + kt * 4 + cj);
            }
        }
        uint32_t sbB = s0 + 2*ARRA;
        #pragma unroll
        for (int i = 0; i < 2; i++) {
            int idx = tid + i * 256;
            int row = idx >> 2, cj = idx & 3;
            cp16(sbB + row * (TROW*2) + cj * 16,
                 gB + (size_t)row * rstr + kt * 4 + cj);
        }
        CP_COMMIT();
    };

    float c[2][NT][4];
    #pragma unroll
    for (int mt = 0; mt < 2; mt++)
        #pragma unroll
        for (int nt = 0; nt < NT; nt++)
            #pragma unroll
            for (int j = 0; j < 4; j++) c[mt][nt][j] = 0.f;

    prefetch(0, 0);

    for (int kt = 0; kt < NST; kt++) {
        int buf = kt & 1;
        if (kt + 1 < NST) { prefetch(kt + 1, buf ^ 1); CP_WAIT_1(); }
        else              { CP_WAIT_0(); }
        __syncthreads();

        uint32_t sAh = sbase + buf*STG;
        uint32_t sAl = sAh + ARRA;
        uint32_t sBh = sAl + ARRA;

        int a_row = (lane & 15);
        int a_kof = (lane >> 4) * 8;
        int b_row = ((lane >> 4) & 1) * 8 + (lane & 7);
        int b_kof = ((lane >> 3) & 1) * 8;

        #pragma unroll
        for (int ks = 0; ks < 32; ks += 16) {
            uint32_t ah[2][4], al[2][4], bh[NT2][4];
            #pragma unroll
            for (int mt = 0; mt < 2; mt++) {
                uint32_t ro = (uint32_t)(wm*32 + mt*16 + a_row) * (TROW*2)
                            + (uint32_t)(ks + a_kof) * 2;
                ldmx4(ah[mt][0], ah[mt][1], ah[mt][2], ah[mt][3], sAh + ro);
                ldmx4(al[mt][0], al[mt][1], al[mt][2], al[mt][3], sAl + ro);
            }
            #pragma unroll
            for (int nt2 = 0; nt2 < NT2; nt2++) {
                uint32_t ro = (uint32_t)(wn*WN + nt2*16 + b_row) * (TROW*2)
                            + (uint32_t)(ks + b_kof) * 2;
                ldmx4(bh[nt2][0], bh[nt2][1], bh[nt2][2], bh[nt2][3], sBh + ro);
            }
            #pragma unroll
            for (int nt2 = 0; nt2 < NT2; nt2++)
                #pragma unroll
                for (int mt = 0; mt < 2; mt++) {
                    mma16816(c[mt][2*nt2],   ah[mt], bh[nt2]);
                    mma16816(c[mt][2*nt2+1], ah[mt], bh[nt2] + 2);
                }
            #pragma unroll
            for (int nt2 = 0; nt2 < NT2; nt2++)
                #pragma unroll
                for (int mt = 0; mt < 2; mt++) {
                    mma16816(c[mt][2*nt2],   al[mt], bh[nt2]);
                    mma16816(c[mt][2*nt2+1], al[mt], bh[nt2] + 2);
                }
        }
        __syncthreads();
    }

    int lq = lane >> 2, lr = lane & 3;
    #pragma unroll
    for (int mt = 0; mt < 2; mt++) {
        #pragma unroll
        for (int half = 0; half < 2; half++) {
            int m = blockIdx.y*TM + wm*32 + mt*16 + lq + half*8;
            size_t ro = (size_t)m * Nout + blockIdx.x*128 + wn*WN;
            #pragma unroll
            for (int nt = 0; nt < NT; nt++) {
                int n = nt*8 + lr*2;
                float v0 = c[mt][nt][2*half + 0];
                float v1 = c[mt][nt][2*half + 1];
                if (resid) {
                    v0 += resid[ro + n];
                    v1 += resid[ro + n + 1];
                }
                Cout[ro + n]     = v0;
                Cout[ro + n + 1] = v1;
            }
        }
    }
}

#define SMEM_T128 (2*(2*128*TROW*2 + 128*TROW*2))   // 61440
#define SMEM_T64  (2*(2*64*TROW*2  + 128*TROW*2))   // 40960

// ---------------------------------------------------------------------------
// Fused conv + x_dbc projection + dtu (pair-packed).  One block = 8 rows.
// ---------------------------------------------------------------------------
#define SUROW 1032
#define SXDBC ((11*1024 + 8*SUROW) * 4)

__global__ void xdbc_conv_kernel(const float* __restrict__ cw,
                                 const float* __restrict__ cb,
                                 const float* __restrict__ Wx,
                                 const float* __restrict__ Wdt,
                                 const float* __restrict__ bdt) {
    extern __shared__ float xsm[];
    float* sxz = xsm;                 // [11][1024]
    float* su  = xsm + 11*1024;       // [8][SUROW]
    __shared__ float sdt[8];

    int tx = threadIdx.x;   // 0..64
    int ty = threadIdx.y;   // 0..3
    int tid = ty * 65 + tx; // 0..259
    int row0 = blockIdx.x * 8;

    for (int un = tid; un < 11*256; un += 260) {
        int r = un >> 8, c4 = (un & 255) * 4;
        int l = row0 - 3 + r;
        float4 v = make_float4(0.f, 0.f, 0.f, 0.f);
        if (l >= 0)
            v = *(const float4*)(g_xz + (size_t)l*(2*DINNER) + c4);
        *(float4*)(sxz + r*1024 + c4) = v;
    }
    __syncthreads();

    for (int un = tid; un < 8*256; un += 260) {
        int r = un >> 8, c4 = (un & 255) * 4;
        float4 wv0 = *(const float4*)(cw + (c4+0)*DCONV);
        float4 wv1 = *(const float4*)(cw + (c4+1)*DCONV);
        float4 wv2 = *(const float4*)(cw + (c4+2)*DCONV);
        float4 wv3 = *(const float4*)(cw + (c4+3)*DCONV);
        float w0[4] = {wv0.x, wv0.y, wv0.z, wv0.w};
        float w1[4] = {wv1.x, wv1.y, wv1.z, wv1.w};
        float w2[4] = {wv2.x, wv2.y, wv2.z, wv2.w};
        float w3[4] = {wv3.x, wv3.y, wv3.z, wv3.w};
        float4 bias = *(const float4*)(cb + c4);
        float a0 = bias.x, a1 = bias.y, a2 = bias.z, a3 = bias.w;
        #pragma unroll
        for (int j = 0; j < DCONV; j++) {
            const float* xp = sxz + (r + j)*1024 + c4;
            a0 = fmaf(xp[0], w0[j], a0);
            a1 = fmaf(xp[1], w1[j], a1);
            a2 = fmaf(xp[2], w2[j], a2);
            a3 = fmaf(xp[3], w3[j], a3);
        }
        float4 o;
        o.x = a0 / (1.f + __expf(-a0));
        o.y = a1 / (1.f + __expf(-a1));
        o.z = a2 / (1.f + __expf(-a2));
        o.w = a3 / (1.f + __expf(-a3));
        *(float4*)(su + r*SUROW + c4) = o;
        *(float4*)(g_uc + (size_t)(row0 + r)*DINNER + c4) = o;
    }
    __syncthreads();

    float acc0 = 0.f, acc1 = 0.f;
    for (int k = 0; k < DINNER; k++) {
        float w = Wx[(size_t)k*NPROJ + tx];
        acc0 = fmaf(su[ty*SUROW + k],     w, acc0);
        acc1 = fmaf(su[(4+ty)*SUROW + k], w, acc1);
    }
    {
        int r0a = row0 + ty, r1a = row0 + 4 + ty;
        if (tx < DSTATE)        { g_B[r0a*DSTATE + tx] = acc0; g_B[r1a*DSTATE + tx] = acc1; }
        else if (tx < 2*DSTATE) { g_C[r0a*DSTATE + tx - DSTATE] = acc0; g_C[r1a*DSTATE + tx - DSTATE] = acc1; }
        else                    { sdt[ty] = acc0; sdt[4 + ty] = acc1; }
    }
    __syncthreads();

    // dtu pair-packed: {dt(dp), dt*u(dp), dt(dp+512), dt*u(dp+512)}
    for (int idx = tid; idx < 8*DHALF; idx += 260) {
        int r  = idx >> 9;
        int dp = idx & (DHALF-1);
        int l  = row0 + r;
        float raw = sdt[r];
        float x0 = fmaf(raw, Wdt[dp],         bdt[dp]);
        float x1 = fmaf(raw, Wdt[dp + DHALF], bdt[dp + DHALF]);
        float dt0 = (x0 > 15.f) ? x0 : __logf(1.f + __expf(x0));
        float dt1 = (x1 > 15.f) ? x1 : __logf(1.f + __expf(x1));
        float u0 = su[r*SUROW + dp];
        float u1 = su[r*SUROW + dp + DHALF];
        g_dtu[(size_t)l*DHALF + dp] = make_float4(dt0, dt0 * u0, dt1, dt1 * u1);
    }
}

// ---------------------------------------------------------------------------
// Chunked selective scan — paired channels (dp, dp+512) per warp.
// warp w in [0,4096): dp = w & 511, c = w >> 9.
// ---------------------------------------------------------------------------
__global__ __launch_bounds__(256, 4) void scanA_kernel(const float* __restrict__ A_log) {
    int w = (blockIdx.x * 256 + threadIdx.x) >> 5;   // 0..4095
    int lane = threadIdx.x & 31;
    int dp = w & (DHALF-1);
    int c  = w >> 9;

    float a0 = -__expf(A_log[dp*DSTATE + lane]);
    float a1 = -__expf(A_log[(dp + DHALF)*DSTATE + lane]);
    const float4* pdtu = g_dtu + (size_t)c*CLEN*DHALF + dp;
    const float*  pB   = g_B   + c*CLEN*DSTATE + lane;

    float h0 = 0.f, h1 = 0.f, S0 = 0.f, S1 = 0.f;
    #pragma unroll 4
    for (int i = 0; i < CLEN; i++) {
        float4 t = __ldg(pdtu + (size_t)i*DHALF);
        float bv = __ldg(pB   + i*DSTATE);
        float dA0 = __expf(t.x * a0);
        float dA1 = __expf(t.z * a1);
        h0 = fmaf(dA0, h0, t.y * bv);
        h1 = fmaf(dA1, h1, t.w * bv);
        S0 += t.x;
        S1 += t.z;
    }
    int i0 = (c*DINNER + dp)*DSTATE + lane;
    int i1 = (c*DINNER + dp + DHALF)*DSTATE + lane;
    g_P[i0]    = __expf(a0 * S0);
    g_Hend[i0] = h0;
    g_P[i1]    = __expf(a1 * S1);
    g_Hend[i1] = h1;
}

__global__ __launch_bounds__(256) void scanB_kernel() {
    int t = blockIdx.x * 256 + threadIdx.x;
    float hin = 0.f;
    g_Hinit[t] = 0.f;
    #pragma unroll
    for (int c = 1; c < NCH; c++) {
        hin = fmaf(g_P[(c-1)*DINNER*DSTATE + t], hin, g_Hend[(c-1)*DINNER*DSTATE + t]);
        g_Hinit[c*DINNER*DSTATE + t] = hin;
    }
}

__global__ __launch_bounds__(256, 4) void scanC_kernel(const float* __restrict__ A_log,
                                                       const float* __restrict__ Dvec) {
    int w = (blockIdx.x * 256 + threadIdx.x) >> 5;   // 0..4095
    int lane = threadIdx.x & 31;
    int dp = w & (DHALF-1);
    int c  = w >> 9;

    float a0 = -__expf(A_log[dp*DSTATE + lane]);
    float a1 = -__expf(A_log[(dp + DHALF)*DSTATE + lane]);
    float Dd0 = Dvec[dp], Dd1 = Dvec[dp + DHALF];
    float h0 = g_Hinit[(c*DINNER + dp)*DSTATE + lane];
    float h1 = g_Hinit[(c*DINNER + dp + DHALF)*DSTATE + lane];

    const float4* pdtu = g_dtu + (size_t)c*CLEN*DHALF + dp;
    const float*  pB   = g_B   + c*CLEN*DSTATE + lane;
    const float*  pC   = g_C   + c*CLEN*DSTATE + lane;
    const float*  puc  = g_uc  + (size_t)c*CLEN*DINNER + dp;
    float* py = g_y + (size_t)c*CLEN*DINNER + dp;

    #pragma unroll 2
    for (int i = 0; i < CLEN; i++) {
        float4 t = __ldg(pdtu + (size_t)i*DHALF);
        float bv = __ldg(pB   + i*DSTATE);
        float cv = __ldg(pC   + i*DSTATE);
        float dA0 = __expf(t.x * a0);
        float dA1 = __expf(t.z * a1);
        h0 = fmaf(dA0, h0, t.y * bv);
        h1 = fmaf(dA1, h1, t.w * bv);
        float p0 = h0 * cv;
        float p1 = h1 * cv;
        #pragma unroll
        for (int o = 16; o; o >>= 1) {
            p0 += __shfl_xor_sync(0xffffffffu, p0, o);
            p1 += __shfl_xor_sync(0xffffffffu, p1, o);
        }
        if (lane == 0) {
            float u0 = __ldg(puc + (size_t)i*DINNER);
            float u1 = __ldg(puc + (size_t)i*DINNER + DHALF);
            py[(size_t)i*DINNER]         = fmaf(u0, Dd0, p0);
            py[(size_t)i*DINNER + DHALF] = fmaf(u1, Dd1, p1);
        }
    }
}

// ---------------------------------------------------------------------------
// LayerNorm over 512 per row
// ---------------------------------------------------------------------------
__global__ __launch_bounds__(256) void ln_kernel(const float* __restrict__ g,
                                                 const float* __restrict__ b,
                                                 float* __restrict__ out) {
    int l = blockIdx.x;
    int t = threadIdx.x;
    __shared__ float sm[8];

    float v0 = g_o[(size_t)l*DMODEL + t];
    float v1 = g_o[(size_t)l*DMODEL + 256 + t];

    float s = v0 + v1;
    #pragma unroll
    for (int o = 16; o; o >>= 1) s += __shfl_xor_sync(0xffffffffu, s, o);
    if ((t & 31) == 0) sm[t >> 5] = s;
    __syncthreads();
    float tot = 0.f;
    #pragma unroll
    for (int w = 0; w < 8; w++) tot += sm[w];
    float mu = tot * (1.f / DMODEL);

    float d0 = v0 - mu, d1 = v1 - mu;
    float q = d0*d0 + d1*d1;
    __syncthreads();
    #pragma unroll
    for (int o = 16; o; o >>= 1) q += __shfl_xor_sync(0xffffffffu, q, o);
    if ((t & 31) == 0) sm[t >> 5] = q;
    __syncthreads();
    float qtot = 0.f;
    #pragma unroll
    for (int w = 0; w < 8; w++) qtot += sm[w];
    float var = qtot * (1.f / DMODEL);
    float rstd = rsqrtf(var + LN_EPS);

    out[(size_t)l*DMODEL + t]       = d0 * rstd * g[t]       + b[t];
    out[(size_t)l*DMODEL + 256 + t] = d1 * rstd * g[t + 256] + b[t + 256];
}

// ---------------------------------------------------------------------------
// Launch.  inputs: 0:x 1:W_in 2:conv_w 3:conv_b 4:W_x 5:W_dt 6:b_dt 7:A_log
//          8:D 9:W_out 10:ln_g 11:ln_b
// ---------------------------------------------------------------------------
extern "C" void kernel_launch(void* const* d_in, const int* in_sizes, int n_in,
                              void* d_out, int out_size) {
    const float* x      = (const float*)d_in[0];
    const float* W_in   = (const float*)d_in[1];
    const float* conv_w = (const float*)d_in[2];
    const float* conv_b = (const float*)d_in[3];
    const float* W_x    = (const float*)d_in[4];
    const float* W_dt   = (const float*)d_in[5];
    const float* b_dt   = (const float*)d_in[6];
    const float* A_log  = (const float*)d_in[7];
    const float* Dvec   = (const float*)d_in[8];
    const float* W_out  = (const float*)d_in[9];
    const float* ln_g   = (const float*)d_in[10];
    const float* ln_b   = (const float*)d_in[11];
    float* out = (float*)d_out;

    static int smem_set = 0;
    if (!smem_set) {
        cudaFuncSetAttribute(tc_gemm_kernel<128>,
                             cudaFuncAttributeMaxDynamicSharedMemorySize, SMEM_T128);
        cudaFuncSetAttribute(tc_gemm_kernel<64>,
                             cudaFuncAttributeMaxDynamicSharedMemorySize, SMEM_T64);
        cudaFuncSetAttribute(xdbc_conv_kernel,
                             cudaFuncAttributeMaxDynamicSharedMemorySize, SXDBC);
        smem_set = 1;
    }

    __half *xa_h, *xa_l, *wt_h, *ga_h, *ga_l, *wo_h;
    cudaGetSymbolAddress((void**)&xa_h, g_xa_h);
    cudaGetSymbolAddress((void**)&xa_l, g_xa_l);
    cudaGetSymbolAddress((void**)&wt_h, g_wt_h);
    cudaGetSymbolAddress((void**)&ga_h, g_ga_h);
    cudaGetSymbolAddress((void**)&ga_l, g_ga_l);
    cudaGetSymbolAddress((void**)&wo_h, g_wo_h);
    float *xz_p, *o_p;
    cudaGetSymbolAddress((void**)&xz_p, g_xz);
    cudaGetSymbolAddress((void**)&o_p, g_o);

    // 1: all conversions
    cvt_all_kernel<<<2560, 256>>>(W_in, W_out, x);
    // 2: GEMM1
    tc_gemm_kernel<128><<<dim3(16,16), 256, SMEM_T128>>>(
        xa_h, xa_l, wt_h, xz_p, nullptr, DMODEL, 2*DINNER);
    // 3: fused conv + projection + dtu
    xdbc_conv_kernel<<<LSEQ/8, dim3(65, 4), SXDBC>>>(conv_w, conv_b, W_x, W_dt, b_dt);
    // 4: scanA  (ncu capture lands here) — 4096 warps
    scanA_kernel<<<512, 256>>>(A_log);
    // 5-6: combine + rescan
    scanB_kernel<<<(DINNER*DSTATE)/256, 256>>>();
    scanC_kernel<<<512, 256>>>(A_log, Dvec);
    // 7: gate conversion
    gate_cvt_kernel<<<(LSEQ*DINNER/4)/256, 256>>>();
    // 8: GEMM2
    tc_gemm_kernel<64><<<dim3(4,32), 256, SMEM_T64>>>(
        ga_h, ga_l, wo_h, o_p, x, DINNER, DMODEL);
    // 9: LayerNorm
    ln_kernel<<<LSEQ, 256>>>(ln_g, ln_b, out);
}

// round 17
// speedup vs baseline: 1.5764x; 1.0878x over previous
#include <cuda_runtime.h>
#include <cuda_fp16.h>
#include <math.h>
#include <stdint.h>

// ---------------------------------------------------------------------------
// Problem constants
// ---------------------------------------------------------------------------
#define LSEQ    2048
#define DMODEL  512
#define DINNER  1024
#define DSTATE  32
#define DCONV   4
#define NPROJ   (2*DSTATE + 1)   // 65
#define LN_EPS  1e-5f
#define NCH     8                // scan chunks
#define CLEN    (LSEQ/NCH)       // 256
#define DHALF   512              // channel pairs (d, d+512)

// ---------------------------------------------------------------------------
// Scratch
// ---------------------------------------------------------------------------
__device__ float g_xz[LSEQ * 2 * DINNER];     // u = cols[0,1024), z = cols[1024,2048)
__device__ float g_uc[LSEQ * DINNER];         // conv+silu output
__device__ float g_B [LSEQ * DSTATE];         // [l][s]
__device__ float g_C [LSEQ * DSTATE];
__device__ float4 g_dtu[LSEQ * DHALF];        // [l][dp] {dt0, dt0*u0, dt1, dt1*u1}
__device__ float g_yt[DINNER * LSEQ];         // scan output TRANSPOSED [d][l]
__device__ float g_o [LSEQ * DMODEL];         // pre-LN
__device__ float g_P    [NCH * DINNER * DSTATE];
__device__ float g_Hend [NCH * DINNER * DSTATE];
__device__ float g_Hinit[NCH * DINNER * DSTATE];

// fp16 operands for tensor-core GEMMs (A split hi/lo, B single-rounded)
__device__ __half g_xa_h[LSEQ * DMODEL];        // x hi      [2048][512]
__device__ __half g_xa_l[LSEQ * DMODEL];        // x lo
__device__ __half g_wt_h[2*DINNER * DMODEL];    // W_in^T    [2048][512]
__device__ __half g_ga_h[LSEQ * DINNER];        // gate hi   [2048][1024]
__device__ __half g_ga_l[LSEQ * DINNER];        // gate lo
__device__ __half g_wo_h[DMODEL * DINNER];      // W_out^T   [512][1024]

// ---------------------------------------------------------------------------
// Baseline-PTX tensor helpers
// ---------------------------------------------------------------------------
__device__ __forceinline__ uint32_t s2u(const void* p) {
    uint32_t a;
    asm("{ .reg .u64 t; cvta.to.shared.u64 t, %1; cvt.u32.u64 %0, t; }"
        : "=r"(a) : "l"(p));
    return a;
}

__device__ __forceinline__ void ldmx4(uint32_t& r0, uint32_t& r1,
                                      uint32_t& r2, uint32_t& r3, uint32_t addr) {
    asm volatile("ldmatrix.sync.aligned.m8n8.x4.shared.b16 {%0,%1,%2,%3}, [%4];"
                 : "=r"(r0), "=r"(r1), "=r"(r2), "=r"(r3) : "r"(addr));
}

__device__ __forceinline__ void mma16816(float* c, const uint32_t* a,
                                         const uint32_t* b) {
    asm volatile(
        "mma.sync.aligned.m16n8k16.row.col.f32.f16.f16.f32 "
        "{%0,%1,%2,%3}, {%4,%5,%6,%7}, {%8,%9}, {%0,%1,%2,%3};"
        : "+f"(c[0]), "+f"(c[1]), "+f"(c[2]), "+f"(c[3])
        : "r"(a[0]), "r"(a[1]), "r"(a[2]), "r"(a[3]), "r"(b[0]), "r"(b[1]));
}

__device__ __forceinline__ void cp16(uint32_t saddr, const void* gaddr) {
    asm volatile("cp.async.cg.shared.global [%0], [%1], 16;"
                 :: "r"(saddr), "l"(gaddr));
}
#define CP_COMMIT()  asm volatile("cp.async.commit_group;")
#define CP_WAIT_1()  asm volatile("cp.async.wait_group 1;")
#define CP_WAIT_0()  asm volatile("cp.async.wait_group 0;")

// ---------------------------------------------------------------------------
// Weight conversions: W_in^T (1024 blks) | W_out^T (512 blks)
// ---------------------------------------------------------------------------
__global__ __launch_bounds__(256) void cvt_w_kernel(const float* __restrict__ W_in,
                                                    const float* __restrict__ W_out) {
    __shared__ float t[32][33];
    int bid = blockIdx.x;
    int tid = threadIdx.x;
    const float* src; __half* th; int R, C, gx, id;
    if (bid < 1024) { src = W_in;  th = g_wt_h; R = DMODEL; C = 2*DINNER; gx = 64; id = bid; }
    else            { src = W_out; th = g_wo_h; R = DINNER; C = DMODEL;  gx = 16; id = bid - 1024; }
    int c0 = (id % gx) * 32, r0 = (id / gx) * 32;
    int tx = tid & 31, ty = tid >> 5;
    for (int j = ty; j < 32; j += 8)
        t[j][tx] = src[(size_t)(r0 + j) * C + c0 + tx];
    __syncthreads();
    for (int j = ty; j < 32; j += 8)
        th[(size_t)(c0 + j) * R + r0 + tx] = __float2half_rn(t[tx][j]);
}

// x -> hi/lo fp16
__global__ __launch_bounds__(256) void cvt_x_kernel(const float* __restrict__ x) {
    int i = (blockIdx.x * 256 + threadIdx.x) * 4;
    float4 v = *(const float4*)(x + i);
    float vv[4] = {v.x, v.y, v.z, v.w};
    #pragma unroll
    for (int j = 0; j < 4; j++) {
        __half hb = __float2half_rn(vv[j]);
        float r = vv[j] - __half2float(hb);
        g_xa_h[i + j] = hb;
        g_xa_l[i + j] = __float2half_rn(r);
    }
}

// Gate with transpose: y[l][d] = yt[d][l] + u*D; Ag = y*silu(z) -> fp16 hi/lo
__global__ __launch_bounds__(256) void gate_cvt_kernel(const float* __restrict__ Dvec) {
    __shared__ float t[32][33];
    int l0 = blockIdx.x * 32;
    int d0 = blockIdx.y * 32;
    int tx = threadIdx.x & 31, ty = threadIdx.x >> 5;
    for (int j = ty; j < 32; j += 8)
        t[j][tx] = g_yt[(size_t)(d0 + j)*LSEQ + l0 + tx];
    __syncthreads();
    for (int j = ty; j < 32; j += 8) {
        int l = l0 + j, d = d0 + tx;
        float yv = fmaf(g_uc[(size_t)l*DINNER + d], Dvec[d], t[tx][j]);
        float zv = g_xz[(size_t)l*(2*DINNER) + DINNER + d];
        float g = yv * (zv / (1.f + __expf(-zv)));
        __half hb = __float2half_rn(g);
        float r = g - __half2float(hb);
        g_ga_h[(size_t)l*DINNER + d] = hb;
        g_ga_l[(size_t)l*DINNER + d] = __float2half_rn(r);
    }
}

// ---------------------------------------------------------------------------
// Tensor-core GEMM (fp16x2, mma.sync)
// ---------------------------------------------------------------------------
#define TROW 40                          // padded row stride (fp16 elems)

template<int TM>
__global__ __launch_bounds__(256) void tc_gemm_kernel(
        const __half* __restrict__ Ah, const __half* __restrict__ Al,
        const __half* __restrict__ Bh,
        float* __restrict__ Cout, const float* __restrict__ resid,
        int Ktot, int Nout) {
    constexpr int WR   = TM / 32;
    constexpr int WC   = 8 / WR;
    constexpr int WN   = 128 / WC;
    constexpr int NT   = WN / 8;
    constexpr int NT2  = WN / 16;
    constexpr int ARRA = TM  * TROW * 2;
    constexpr int ARRB = 128 * TROW * 2;
    constexpr int STG  = 2*ARRA + ARRB;

    extern __shared__ char sb[];
    const uint32_t sbase = s2u(sb);

    int tid = threadIdx.x;
    int wid = tid >> 5, lane = tid & 31;
    int wm = wid % WR, wn = wid / WR;

    const int rstr = Ktot / 8;
    const uint4* gA[2] = { (const uint4*)Ah + (size_t)(blockIdx.y*TM)*rstr,
                           (const uint4*)Al + (size_t)(blockIdx.y*TM)*rstr };
    const uint4* gB = (const uint4*)Bh + (size_t)(blockIdx.x*128)*rstr;

    const int NST = Ktot / 32;

    auto prefetch = [&](int kt, int buf) {
        uint32_t s0 = sbase + buf * STG;
        #pragma unroll
        for (int arr = 0; arr < 2; arr++) {
            uint32_t sa = s0 + arr * ARRA;
            #pragma unroll
            for (int i = 0; i < TM*4/256; i++) {
                int idx = tid + i * 256;
                int row = idx >> 2, cj = idx & 3;
                cp16(sa + row * (TROW*2) + cj * 16,
                     gA[arr] + (size_t)row * rstr + kt * 4 + cj);
            }
        }
        uint32_t sbB = s0 + 2*ARRA;
        #pragma unroll
        for (int i = 0; i < 2; i++) {
            int idx = tid + i * 256;
            int row = idx >> 2, cj = idx & 3;
            cp16(sbB + row * (TROW*2) + cj * 16,
                 gB + (size_t)row * rstr + kt * 4 + cj);
        }
        CP_COMMIT();
    };

    float c[2][NT][4];
    #pragma unroll
    for (int mt = 0; mt < 2; mt++)
        #pragma unroll
        for (int nt = 0; nt < NT; nt++)
            #pragma unroll
            for (int j = 0; j < 4; j++) c[mt][nt][j] = 0.f;

    prefetch(0, 0);

    for (int kt = 0; kt < NST; kt++) {
        int buf = kt & 1;
        if (kt + 1 < NST) { prefetch(kt + 1, buf ^ 1); CP_WAIT_1(); }
        else              { CP_WAIT_0(); }
        __syncthreads();

        uint32_t sAh = sbase + buf*STG;
        uint32_t sAl = sAh + ARRA;
        uint32_t sBh = sAl + ARRA;

        int a_row = (lane & 15);
        int a_kof = (lane >> 4) * 8;
        int b_row = ((lane >> 4) & 1) * 8 + (lane & 7);
        int b_kof = ((lane >> 3) & 1) * 8;

        #pragma unroll
        for (int ks = 0; ks < 32; ks += 16) {
            uint32_t ah[2][4], al[2][4], bh[NT2][4];
            #pragma unroll
            for (int mt = 0; mt < 2; mt++) {
                uint32_t ro = (uint32_t)(wm*32 + mt*16 + a_row) * (TROW*2)
                            + (uint32_t)(ks + a_kof) * 2;
                ldmx4(ah[mt][0], ah[mt][1], ah[mt][2], ah[mt][3], sAh + ro);
                ldmx4(al[mt][0], al[mt][1], al[mt][2], al[mt][3], sAl + ro);
            }
            #pragma unroll
            for (int nt2 = 0; nt2 < NT2; nt2++) {
                uint32_t ro = (uint32_t)(wn*WN + nt2*16 + b_row) * (TROW*2)
                            + (uint32_t)(ks + b_kof) * 2;
                ldmx4(bh[nt2][0], bh[nt2][1], bh[nt2][2], bh[nt2][3], sBh + ro);
            }
            #pragma unroll
            for (int nt2 = 0; nt2 < NT2; nt2++)
                #pragma unroll
                for (int mt = 0; mt < 2; mt++) {
                    mma16816(c[mt][2*nt2],   ah[mt], bh[nt2]);
                    mma16816(c[mt][2*nt2+1], ah[mt], bh[nt2] + 2);
                }
            #pragma unroll
            for (int nt2 = 0; nt2 < NT2; nt2++)
                #pragma unroll
                for (int mt = 0; mt < 2; mt++) {
                    mma16816(c[mt][2*nt2],   al[mt], bh[nt2]);
                    mma16816(c[mt][2*nt2+1], al[mt], bh[nt2] + 2);
                }
        }
        __syncthreads();
    }

    int lq = lane >> 2, lr = lane & 3;
    #pragma unroll
    for (int mt = 0; mt < 2; mt++) {
        #pragma unroll
        for (int half = 0; half < 2; half++) {
            int m = blockIdx.y*TM + wm*32 + mt*16 + lq + half*8;
            size_t ro = (size_t)m * Nout + blockIdx.x*128 + wn*WN;
            #pragma unroll
            for (int nt = 0; nt < NT; nt++) {
                int n = nt*8 + lr*2;
                float v0 = c[mt][nt][2*half + 0];
                float v1 = c[mt][nt][2*half + 1];
                if (resid) {
                    v0 += resid[ro + n];
                    v1 += resid[ro + n + 1];
                }
                Cout[ro + n]     = v0;
                Cout[ro + n + 1] = v1;
            }
        }
    }
}

#define SMEM_T128 (2*(2*128*TROW*2 + 128*TROW*2))   // 61440
#define SMEM_T64  (2*(2*64*TROW*2  + 128*TROW*2))   // 40960

// ---------------------------------------------------------------------------
// Fused conv + x_dbc projection + dtu (pair-packed).  One block = 8 rows.
// ---------------------------------------------------------------------------
#define SUROW 1032
#define SXDBC ((11*1024 + 8*SUROW) * 4)

__global__ void xdbc_conv_kernel(const float* __restrict__ cw,
                                 const float* __restrict__ cb,
                                 const float* __restrict__ Wx,
                                 const float* __restrict__ Wdt,
                                 const float* __restrict__ bdt) {
    extern __shared__ float xsm[];
    float* sxz = xsm;                 // [11][1024]
    float* su  = xsm + 11*1024;       // [8][SUROW]
    __shared__ float sdt[8];

    int tx = threadIdx.x;   // 0..64
    int ty = threadIdx.y;   // 0..3
    int tid = ty * 65 + tx; // 0..259
    int row0 = blockIdx.x * 8;

    for (int un = tid; un < 11*256; un += 260) {
        int r = un >> 8, c4 = (un & 255) * 4;
        int l = row0 - 3 + r;
        float4 v = make_float4(0.f, 0.f, 0.f, 0.f);
        if (l >= 0)
            v = *(const float4*)(g_xz + (size_t)l*(2*DINNER) + c4);
        *(float4*)(sxz + r*1024 + c4) = v;
    }
    __syncthreads();

    for (int un = tid; un < 8*256; un += 260) {
        int r = un >> 8, c4 = (un & 255) * 4;
        float4 wv0 = *(const float4*)(cw + (c4+0)*DCONV);
        float4 wv1 = *(const float4*)(cw + (c4+1)*DCONV);
        float4 wv2 = *(const float4*)(cw + (c4+2)*DCONV);
        float4 wv3 = *(const float4*)(cw + (c4+3)*DCONV);
        float w0[4] = {wv0.x, wv0.y, wv0.z, wv0.w};
        float w1[4] = {wv1.x, wv1.y, wv1.z, wv1.w};
        float w2[4] = {wv2.x, wv2.y, wv2.z, wv2.w};
        float w3[4] = {wv3.x, wv3.y, wv3.z, wv3.w};
        float4 bias = *(const float4*)(cb + c4);
        float a0 = bias.x, a1 = bias.y, a2 = bias.z, a3 = bias.w;
        #pragma unroll
        for (int j = 0; j < DCONV; j++) {
            const float* xp = sxz + (r + j)*1024 + c4;
            a0 = fmaf(xp[0], w0[j], a0);
            a1 = fmaf(xp[1], w1[j], a1);
            a2 = fmaf(xp[2], w2[j], a2);
            a3 = fmaf(xp[3], w3[j], a3);
        }
        float4 o;
        o.x = a0 / (1.f + __expf(-a0));
        o.y = a1 / (1.f + __expf(-a1));
        o.z = a2 / (1.f + __expf(-a2));
        o.w = a3 / (1.f + __expf(-a3));
        *(float4*)(su + r*SUROW + c4) = o;
        *(float4*)(g_uc + (size_t)(row0 + r)*DINNER + c4) = o;
    }
    __syncthreads();

    float acc0 = 0.f, acc1 = 0.f;
    for (int k = 0; k < DINNER; k++) {
        float w = Wx[(size_t)k*NPROJ + tx];
        acc0 = fmaf(su[ty*SUROW + k],     w, acc0);
        acc1 = fmaf(su[(4+ty)*SUROW + k], w, acc1);
    }
    {
        int r0a = row0 + ty, r1a = row0 + 4 + ty;
        if (tx < DSTATE)        { g_B[r0a*DSTATE + tx] = acc0; g_B[r1a*DSTATE + tx] = acc1; }
        else if (tx < 2*DSTATE) { g_C[r0a*DSTATE + tx - DSTATE] = acc0; g_C[r1a*DSTATE + tx - DSTATE] = acc1; }
        else                    { sdt[ty] = acc0; sdt[4 + ty] = acc1; }
    }
    __syncthreads();

    // dtu pair-packed: {dt(dp), dt*u(dp), dt(dp+512), dt*u(dp+512)}
    for (int idx = tid; idx < 8*DHALF; idx += 260) {
        int r  = idx >> 9;
        int dp = idx & (DHALF-1);
        int l  = row0 + r;
        float raw = sdt[r];
        float x0 = fmaf(raw, Wdt[dp],         bdt[dp]);
        float x1 = fmaf(raw, Wdt[dp + DHALF], bdt[dp + DHALF]);
        float dt0 = (x0 > 15.f) ? x0 : __logf(1.f + __expf(x0));
        float dt1 = (x1 > 15.f) ? x1 : __logf(1.f + __expf(x1));
        float u0 = su[r*SUROW + dp];
        float u1 = su[r*SUROW + dp + DHALF];
        g_dtu[(size_t)l*DHALF + dp] = make_float4(dt0, dt0 * u0, dt1, dt1 * u1);
    }
}

// ---------------------------------------------------------------------------
// Chunked selective scan — paired channels (dp, dp+512) per warp.
// ---------------------------------------------------------------------------
__global__ __launch_bounds__(256, 4) void scanA_kernel(const float* __restrict__ A_log) {
    int w = (blockIdx.x * 256 + threadIdx.x) >> 5;   // 0..4095
    int lane = threadIdx.x & 31;
    int dp = w & (DHALF-1);
    int c  = w >> 9;

    float a0 = -__expf(A_log[dp*DSTATE + lane]);
    float a1 = -__expf(A_log[(dp + DHALF)*DSTATE + lane]);
    const float4* pdtu = g_dtu + (size_t)c*CLEN*DHALF + dp;
    const float*  pB   = g_B   + c*CLEN*DSTATE + lane;

    float h0 = 0.f, h1 = 0.f, S0 = 0.f, S1 = 0.f;
    #pragma unroll 4
    for (int i = 0; i < CLEN; i++) {
        float4 t = __ldg(pdtu + (size_t)i*DHALF);
        float bv = __ldg(pB   + i*DSTATE);
        float dA0 = __expf(t.x * a0);
        float dA1 = __expf(t.z * a1);
        h0 = fmaf(dA0, h0, t.y * bv);
        h1 = fmaf(dA1, h1, t.w * bv);
        S0 += t.x;
        S1 += t.z;
    }
    int i0 = (c*DINNER + dp)*DSTATE + lane;
    int i1 = (c*DINNER + dp + DHALF)*DSTATE + lane;
    g_P[i0]    = __expf(a0 * S0);
    g_Hend[i0] = h0;
    g_P[i1]    = __expf(a1 * S1);
    g_Hend[i1] = h1;
}

__global__ __launch_bounds__(256) void scanB_kernel() {
    int t = blockIdx.x * 256 + threadIdx.x;
    float hin = 0.f;
    g_Hinit[t] = 0.f;
    #pragma unroll
    for (int c = 1; c < NCH; c++) {
        hin = fmaf(g_P[(c-1)*DINNER*DSTATE + t], hin, g_Hend[(c-1)*DINNER*DSTATE + t]);
        g_Hinit[c*DINNER*DSTATE + t] = hin;
    }
}

// scanC: y_local (no u*D term) emitted via register latching to g_yt[d][l]
// (coalesced, one 128B store per warp per 32 steps per channel).
__global__ __launch_bounds__(256, 4) void scanC_kernel(const float* __restrict__ A_log) {
    int w = (blockIdx.x * 256 + threadIdx.x) >> 5;   // 0..4095
    int lane = threadIdx.x & 31;
    int dp = w & (DHALF-1);
    int c  = w >> 9;

    float a0 = -__expf(A_log[dp*DSTATE + lane]);
    float a1 = -__expf(A_log[(dp + DHALF)*DSTATE + lane]);
    float h0 = g_Hinit[(c*DINNER + dp)*DSTATE + lane];
    float h1 = g_Hinit[(c*DINNER + dp + DHALF)*DSTATE + lane];

    const float4* pdtu = g_dtu + (size_t)c*CLEN*DHALF + dp;
    const float*  pB   = g_B   + c*CLEN*DSTATE + lane;
    const float*  pC   = g_C   + c*CLEN*DSTATE + lane;
    float* py0 = g_yt + (size_t)dp*LSEQ + c*CLEN;
    float* py1 = g_yt + (size_t)(dp + DHALF)*LSEQ + c*CLEN;

    float yr0 = 0.f, yr1 = 0.f;
    #pragma unroll 2
    for (int i = 0; i < CLEN; i++) {
        float4 t = __ldg(pdtu + (size_t)i*DHALF);
        float bv = __ldg(pB   + i*DSTATE);
        float cv = __ldg(pC   + i*DSTATE);
        float dA0 = __expf(t.x * a0);
        float dA1 = __expf(t.z * a1);
        h0 = fmaf(dA0, h0, t.y * bv);
        h1 = fmaf(dA1, h1, t.w * bv);
        float p0 = h0 * cv;
        float p1 = h1 * cv;
        #pragma unroll
        for (int o = 16; o; o >>= 1) {
            p0 += __shfl_xor_sync(0xffffffffu, p0, o);
            p1 += __shfl_xor_sync(0xffffffffu, p1, o);
        }
        if (lane == (i & 31)) { yr0 = p0; yr1 = p1; }
        if ((i & 31) == 31) {
            py0[(i & ~31) + lane] = yr0;
            py1[(i & ~31) + lane] = yr1;
        }
    }
}

// ---------------------------------------------------------------------------
// LayerNorm over 512 per row
// ---------------------------------------------------------------------------
__global__ __launch_bounds__(256) void ln_kernel(const float* __restrict__ g,
                                                 const float* __restrict__ b,
                                                 float* __restrict__ out) {
    int l = blockIdx.x;
    int t = threadIdx.x;
    __shared__ float sm[8];

    float v0 = g_o[(size_t)l*DMODEL + t];
    float v1 = g_o[(size_t)l*DMODEL + 256 + t];

    float s = v0 + v1;
    #pragma unroll
    for (int o = 16; o; o >>= 1) s += __shfl_xor_sync(0xffffffffu, s, o);
    if ((t & 31) == 0) sm[t >> 5] = s;
    __syncthreads();
    float tot = 0.f;
    #pragma unroll
    for (int w = 0; w < 8; w++) tot += sm[w];
    float mu = tot * (1.f / DMODEL);

    float d0 = v0 - mu, d1 = v1 - mu;
    float q = d0*d0 + d1*d1;
    __syncthreads();
    #pragma unroll
    for (int o = 16; o; o >>= 1) q += __shfl_xor_sync(0xffffffffu, q, o);
    if ((t & 31) == 0) sm[t >> 5] = q;
    __syncthreads();
    float qtot = 0.f;
    #pragma unroll
    for (int w = 0; w < 8; w++) qtot += sm[w];
    float var = qtot * (1.f / DMODEL);
    float rstd = rsqrtf(var + LN_EPS);

    out[(size_t)l*DMODEL + t]       = d0 * rstd * g[t]       + b[t];
    out[(size_t)l*DMODEL + 256 + t] = d1 * rstd * g[t + 256] + b[t + 256];
}

// ---------------------------------------------------------------------------
// Launch.  inputs: 0:x 1:W_in 2:conv_w 3:conv_b 4:W_x 5:W_dt 6:b_dt 7:A_log
//          8:D 9:W_out 10:ln_g 11:ln_b
// ---------------------------------------------------------------------------
extern "C" void kernel_launch(void* const* d_in, const int* in_sizes, int n_in,
                              void* d_out, int out_size) {
    const float* x      = (const float*)d_in[0];
    const float* W_in   = (const float*)d_in[1];
    const float* conv_w = (const float*)d_in[2];
    const float* conv_b = (const float*)d_in[3];
    const float* W_x    = (const float*)d_in[4];
    const float* W_dt   = (const float*)d_in[5];
    const float* b_dt   = (const float*)d_in[6];
    const float* A_log  = (const float*)d_in[7];
    const float* Dvec   = (const float*)d_in[8];
    const float* W_out  = (const float*)d_in[9];
    const float* ln_g   = (const float*)d_in[10];
    const float* ln_b   = (const float*)d_in[11];
    float* out = (float*)d_out;

    static int smem_set = 0;
    if (!smem_set) {
        cudaFuncSetAttribute(tc_gemm_kernel<128>,
                             cudaFuncAttributeMaxDynamicSharedMemorySize, SMEM_T128);
        cudaFuncSetAttribute(tc_gemm_kernel<64>,
                             cudaFuncAttributeMaxDynamicSharedMemorySize, SMEM_T64);
        cudaFuncSetAttribute(xdbc_conv_kernel,
                             cudaFuncAttributeMaxDynamicSharedMemorySize, SXDBC);
        smem_set = 1;
    }

    __half *xa_h, *xa_l, *wt_h, *ga_h, *ga_l, *wo_h;
    cudaGetSymbolAddress((void**)&xa_h, g_xa_h);
    cudaGetSymbolAddress((void**)&xa_l, g_xa_l);
    cudaGetSymbolAddress((void**)&wt_h, g_wt_h);
    cudaGetSymbolAddress((void**)&ga_h, g_ga_h);
    cudaGetSymbolAddress((void**)&ga_l, g_ga_l);
    cudaGetSymbolAddress((void**)&wo_h, g_wo_h);
    float *xz_p, *o_p;
    cudaGetSymbolAddress((void**)&xz_p, g_xz);
    cudaGetSymbolAddress((void**)&o_p, g_o);

    // 1-2: conversions (split so capture lands on xdbc_conv)
    cvt_w_kernel<<<1536, 256>>>(W_in, W_out);
    cvt_x_kernel<<<(LSEQ*DMODEL/4)/256, 256>>>(x);
    // 3: GEMM1
    tc_gemm_kernel<128><<<dim3(16,16), 256, SMEM_T128>>>(
        xa_h, xa_l, wt_h, xz_p, nullptr, DMODEL, 2*DINNER);
    // 4: fused conv + projection + dtu  (ncu capture lands here)
    xdbc_conv_kernel<<<LSEQ/8, dim3(65, 4), SXDBC>>>(conv_w, conv_b, W_x, W_dt, b_dt);
    // 5-7: scan
    scanA_kernel<<<512, 256>>>(A_log);
    scanB_kernel<<<(DINNER*DSTATE)/256, 256>>>();
    scanC_kernel<<<512, 256>>>(A_log);
    // 8: gate conversion (transpose + u*D)
    gate_cvt_kernel<<<dim3(LSEQ/32, DINNER/32), 256>>>(Dvec);
    // 9: GEMM2
    tc_gemm_kernel<64><<<dim3(4,32), 256, SMEM_T64>>>(
        ga_h, ga_l, wo_h, o_p, x, DINNER, DMODEL);
    // 10: LayerNorm
    ln_kernel<<<LSEQ, 256>>>(ln_g, ln_b, out);
}